// round 1
// baseline (speedup 1.0000x reference)
#include <cuda_runtime.h>
#include <cuda_bf16.h>

// out = ((x*2 + 3 - 1) / 2)^2 == (x + 1)^2  (exact simplification in fp32)
// Pure streaming elementwise kernel: HBM-bound. float4 vectorized.

__global__ void __launch_bounds__(256) ew_sq_kernel(const float4* __restrict__ in,
                                                    float4* __restrict__ out,
                                                    int n4) {
    int idx = blockIdx.x * blockDim.x + threadIdx.x;
    int stride = gridDim.x * blockDim.x;
    for (int i = idx; i < n4; i += stride) {
        float4 v = in[i];
        float a = v.x + 1.0f;
        float b = v.y + 1.0f;
        float c = v.z + 1.0f;
        float d = v.w + 1.0f;
        float4 r;
        r.x = a * a;
        r.y = b * b;
        r.z = c * c;
        r.w = d * d;
        out[i] = r;
    }
}

// Tail handler for element counts not divisible by 4 (not needed for 8192^2,
// but keeps the kernel correct for any shape).
__global__ void ew_sq_tail(const float* __restrict__ in, float* __restrict__ out,
                           int start, int n) {
    int i = start + blockIdx.x * blockDim.x + threadIdx.x;
    if (i < n) {
        float t = in[i] + 1.0f;
        out[i] = t * t;
    }
}

extern "C" void kernel_launch(void* const* d_in, const int* in_sizes, int n_in,
                              void* d_out, int out_size) {
    const float* x = (const float*)d_in[0];
    float* out = (float*)d_out;
    int n = in_sizes[0];

    int n4 = n / 4;
    int tail_start = n4 * 4;

    const int threads = 256;
    // ~8 float4s per thread: grid = n4 / (threads * 8), capped to keep full waves.
    int blocks = (n4 + threads * 8 - 1) / (threads * 8);
    if (blocks < 1) blocks = 1;
    // Round to a multiple of SM count's wave capacity isn't critical for a
    // grid-stride loop; just ensure we have plenty of CTAs for all 148+ SMs.
    if (blocks > 65535 * 16) blocks = 65535 * 16;

    if (n4 > 0) {
        ew_sq_kernel<<<blocks, threads>>>((const float4*)x, (float4*)out, n4);
    }
    if (tail_start < n) {
        int tail_n = n - tail_start;
        ew_sq_tail<<<(tail_n + 255) / 256, 256>>>(x, out, tail_start, n);
    }
}

// round 2
// speedup vs baseline: 1.0086x; 1.0086x over previous
#include <cuda_runtime.h>
#include <cuda_bf16.h>

// out = ((x*2 + 3 - 1) / 2)^2 == (x + 1)^2  (exact simplification in fp32)
// HBM-bound streaming kernel. float4 vectorized, x4 unrolled with
// front-batched independent loads (MLP=4/thread) and cache-streaming
// (.cs evict-first) hints since every byte is touched exactly once.

#define UNROLL 4

__global__ void __launch_bounds__(256) ew_sq_kernel(const float4* __restrict__ in,
                                                    float4* __restrict__ out,
                                                    int n4) {
    int base = blockIdx.x * (blockDim.x * UNROLL) + threadIdx.x;
    int gstride = gridDim.x * blockDim.x * UNROLL;

    for (int i0 = base; i0 < n4; i0 += gstride) {
        float4 v[UNROLL];
        bool ok[UNROLL];
        // Front-batch all loads (independent -> MLP = UNROLL)
        #pragma unroll
        for (int k = 0; k < UNROLL; k++) {
            int i = i0 + k * 256;
            ok[k] = (i < n4);
            if (ok[k]) v[k] = __ldcs(in + i);
        }
        #pragma unroll
        for (int k = 0; k < UNROLL; k++) {
            if (ok[k]) {
                float a = v[k].x + 1.0f;
                float b = v[k].y + 1.0f;
                float c = v[k].z + 1.0f;
                float d = v[k].w + 1.0f;
                float4 r;
                r.x = a * a;
                r.y = b * b;
                r.z = c * c;
                r.w = d * d;
                int i = i0 + k * 256;
                __stcs(out + i, r);
            }
        }
    }
}

// Tail for element counts not divisible by 4 (unused for 8192^2).
__global__ void ew_sq_tail(const float* __restrict__ in, float* __restrict__ out,
                           int start, int n) {
    int i = start + blockIdx.x * blockDim.x + threadIdx.x;
    if (i < n) {
        float t = in[i] + 1.0f;
        out[i] = t * t;
    }
}

extern "C" void kernel_launch(void* const* d_in, const int* in_sizes, int n_in,
                              void* d_out, int out_size) {
    const float* x = (const float*)d_in[0];
    float* out = (float*)d_out;
    int n = in_sizes[0];

    int n4 = n / 4;
    int tail_start = n4 * 4;

    const int threads = 256;
    // One pass: each CTA covers threads*UNROLL float4s.
    int blocks = (n4 + threads * UNROLL - 1) / (threads * UNROLL);
    if (blocks < 1) blocks = 1;

    if (n4 > 0) {
        ew_sq_kernel<<<blocks, threads>>>((const float4*)x, (float4*)out, n4);
    }
    if (tail_start < n) {
        int tail_n = n - tail_start;
        ew_sq_tail<<<(tail_n + 255) / 256, 256>>>(x, out, tail_start, n);
    }
}